// round 11
// baseline (speedup 1.0000x reference)
#include <cuda_runtime.h>
#include <cuda_fp16.h>
#include <cstdint>

// ============================================================================
// out = gelu( x @ ((fc1_w^T @ fc2_w^T + b) * mask) )   — fp32 in/out
// fp16 mma.sync.m16n8k16, f32 accumulate (R6/R7 schedule = proven optimum).
// R11: GEMM2 converts x f32->f16 INLINE (LDG.128 register pipeline + STS),
// eliminating the 43us cvt_x prepass. GEMM1 unchanged.
// ============================================================================

__device__ __half g_fc1T[1024 * 4096];
__device__ __half g_fc2h[1024 * 4096];
__device__ float  g_part[4 * 1024 * 1024];
__device__ __half g_attnT[1024 * 1024];

// ---------------- helpers ---------------------------------------------------
__device__ __forceinline__ uint32_t smem_u32(const void* p) {
    uint32_t a;
    asm("{ .reg .u64 t; cvta.to.shared.u64 t, %1; cvt.u32.u64 %0, t; }" : "=r"(a) : "l"(p));
    return a;
}
#define CP_ASYNC16(sdst, gsrc) \
    asm volatile("cp.async.cg.shared.global [%0], [%1], 16;" :: "r"(sdst), "l"(gsrc) : "memory")
#define CP_COMMIT() asm volatile("cp.async.commit_group;" ::: "memory")
#define CP_WAIT1()  asm volatile("cp.async.wait_group 1;" ::: "memory")
#define CP_WAIT0()  asm volatile("cp.async.wait_group 0;" ::: "memory")
#define SWZ128(off) ((off) ^ (((off) >> 3) & 0x70))

__device__ __forceinline__ void ldsm_x4(uint32_t* r, uint32_t addr) {
    asm volatile("ldmatrix.sync.aligned.m8n8.x4.shared.b16 {%0,%1,%2,%3}, [%4];"
                 : "=r"(r[0]), "=r"(r[1]), "=r"(r[2]), "=r"(r[3]) : "r"(addr));
}
// fp16 MMA, fp32 accumulate
__device__ __forceinline__ void mma_f16(float c[4], const uint32_t a[4], const uint32_t* b) {
    asm volatile(
        "mma.sync.aligned.m16n8k16.row.col.f32.f16.f16.f32 "
        "{%0,%1,%2,%3}, {%4,%5,%6,%7}, {%8,%9}, {%0,%1,%2,%3};"
        : "+f"(c[0]), "+f"(c[1]), "+f"(c[2]), "+f"(c[3])
        : "r"(a[0]), "r"(a[1]), "r"(a[2]), "r"(a[3]), "r"(b[0]), "r"(b[1]));
}
__device__ __forceinline__ float gelu_exact(float u) {
    return 0.5f * u * (1.0f + erff(u * 0.7071067811865476f));
}

constexpr int TBYTES = 128 * 128;   // one 128-row x 64-half tile (16KB)

// ---------------------------------------------------------------------------
// GEMM1 (R7-proven): both operands f16 via 3-stage cp.async. f32 acc, raw out.
// A [*,lda], B [*,ldb] k-major halfs, C = A·B^T. blockIdx.z = split-K slice.
// ---------------------------------------------------------------------------
__global__ __launch_bounds__(256, 2) void hgemm1(
    const __half* __restrict__ A, const __half* __restrict__ B, float* __restrict__ C,
    int M, int N, int lda, int ldb, int kSplit)
{
    extern __shared__ __align__(1024) char smem[];
    const uint32_t sb = smem_u32(smem);
    const int tid  = threadIdx.x;
    const int lane = tid & 31;
    const int wid  = tid >> 5;
    const int wm   = (wid & 3) * 32;
    const int wn   = (wid >> 2) * 64;
    const size_t bm = (size_t)blockIdx.y * 128;
    const size_t bn = (size_t)blockIdx.x * 128;

    const __half* Ab = A + (size_t)blockIdx.z * kSplit;
    const __half* Bb = B + (size_t)blockIdx.z * kSplit;

    const int nk = kSplit / 64;
    const int lr = tid >> 3;
    const int lc = tid & 7;
    auto issue = [&](int chunk) {
        const int buf = chunk % 3;
        const uint32_t aBase = sb + buf * TBYTES;
        const uint32_t bBase = sb + 3 * TBYTES + buf * TBYTES;
        const __half* ga = Ab + (bm + lr) * (size_t)lda + chunk * 64 + lc * 8;
        const __half* gb = Bb + (bn + lr) * (size_t)ldb + chunk * 64 + lc * 8;
#pragma unroll
        for (int j = 0; j < 4; j++) {
            CP_ASYNC16(aBase + SWZ128((lr + j * 32) * 128 + lc * 16), ga + (size_t)(j * 32) * lda);
            CP_ASYNC16(bBase + SWZ128((lr + j * 32) * 128 + lc * 16), gb + (size_t)(j * 32) * ldb);
        }
        CP_COMMIT();
    };

    float c[2][8][4];
#pragma unroll
    for (int im = 0; im < 2; im++)
#pragma unroll
        for (int in = 0; in < 8; in++)
#pragma unroll
            for (int q = 0; q < 4; q++) c[im][in][q] = 0.0f;

    issue(0);
    issue(1);

    const int aRow = lane & 15;
    const int aKo  = ((lane >> 4) & 1) * 16;
    const int bRow = (lane & 7) + ((lane >> 4) << 3);
    const int bKo  = ((lane >> 3) & 1) * 16;

    for (int i = 0; i < nk; i++) {
        if (i + 1 < nk) { CP_WAIT1(); } else { CP_WAIT0(); }
        __syncthreads();
        if (i + 2 < nk) issue(i + 2);

        const uint32_t aS = sb + (i % 3) * TBYTES;
        const uint32_t bS = sb + 3 * TBYTES + (i % 3) * TBYTES;
#pragma unroll
        for (int ks = 0; ks < 4; ks++) {
            uint32_t af[2][4];
#pragma unroll
            for (int im = 0; im < 2; im++)
                ldsm_x4(af[im], aS + SWZ128((wm + im * 16 + aRow) * 128 + ks * 32 + aKo));
#pragma unroll
            for (int nb = 0; nb < 4; nb++) {
                uint32_t bf[4];
                ldsm_x4(bf, bS + SWZ128((wn + nb * 16 + bRow) * 128 + ks * 32 + bKo));
#pragma unroll
                for (int im = 0; im < 2; im++) {
                    mma_f16(c[im][nb * 2 + 0], af[im], &bf[0]);
                    mma_f16(c[im][nb * 2 + 1], af[im], &bf[2]);
                }
            }
        }
    }

    float* Cb = C + (size_t)blockIdx.z * ((size_t)M * N);
    const int g  = lane >> 2;
    const int tg = lane & 3;
#pragma unroll
    for (int im = 0; im < 2; im++) {
#pragma unroll
        for (int in = 0; in < 8; in++) {
            const size_t r0 = bm + wm + im * 16 + g;
            const size_t r1 = r0 + 8;
            const size_t cc = bn + wn + in * 8 + tg * 2;
            *reinterpret_cast<float2*>(Cb + r0 * N + cc) = make_float2(c[im][in][0], c[im][in][1]);
            *reinterpret_cast<float2*>(Cb + r1 * N + cc) = make_float2(c[im][in][2], c[im][in][3]);
        }
    }
}

// ---------------------------------------------------------------------------
// GEMM2: A = x (f32, converted inline), B = attnT (f16, cp.async 3-stage).
// A path: LDG.128 f32 -> registers (held across one MMA section) -> cvt ->
// STS f16 into double-buffered smem tile. out = gelu(A·B^T).
// smem: A 2x16KB @ 0, B 3x16KB @ 32KB  (80KB total, 2 CTAs/SM).
// ---------------------------------------------------------------------------
__global__ __launch_bounds__(256, 2) void hgemm2(
    const float* __restrict__ X, const __half* __restrict__ B, float* __restrict__ C,
    int M, int N, int K)
{
    extern __shared__ __align__(1024) char smem[];
    const uint32_t sb = smem_u32(smem);
    const uint32_t sA = sb;                 // 2 x 16KB
    const uint32_t sB = sb + 2 * TBYTES;    // 3 x 16KB
    const int tid  = threadIdx.x;
    const int lane = tid & 31;
    const int wid  = tid >> 5;
    const int wm   = (wid & 3) * 32;
    const int wn   = (wid >> 2) * 64;
    const size_t bm = (size_t)blockIdx.y * 128;
    const size_t bn = (size_t)blockIdx.x * 128;
    const int nk = K / 64;

    // ---- B: cp.async (one commit group per chunk) ----
    const int lr = tid >> 3;
    const int lc = tid & 7;
    auto issueB = [&](int chunk) {
        const uint32_t base = sB + (chunk % 3) * TBYTES;
        const __half* gb = B + (bn + lr) * (size_t)K + chunk * 64 + lc * 8;
#pragma unroll
        for (int j = 0; j < 4; j++)
            CP_ASYNC16(base + SWZ128((lr + j * 32) * 128 + lc * 16), gb + (size_t)(j * 32) * K);
        CP_COMMIT();
    };

    // ---- A: LDG f32 register pipeline ----
    const int ar = tid >> 4;        // base row 0..15 (rows ar + t*16)
    const int ac = tid & 15;        // float4 column 0..15
    float4 v[8];
    auto ldgA = [&](int chunk) {
        const float* g = X + (bm + ar) * (size_t)K + chunk * 64 + ac * 4;
#pragma unroll
        for (int t = 0; t < 8; t++)
            v[t] = *reinterpret_cast<const float4*>(g + (size_t)(t * 16) * K);
    };
    auto stsA = [&](int chunk) {
        char* base = smem + (chunk & 1) * TBYTES;
#pragma unroll
        for (int t = 0; t < 8; t++) {
            __half2 h0 = __floats2half2_rn(v[t].x, v[t].y);
            __half2 h1 = __floats2half2_rn(v[t].z, v[t].w);
            uint2 u;
            u.x = *reinterpret_cast<uint32_t*>(&h0);
            u.y = *reinterpret_cast<uint32_t*>(&h1);
            *reinterpret_cast<uint2*>(base + SWZ128((ar + t * 16) * 128 + ac * 8)) = u;
        }
    };

    float c[2][8][4];
#pragma unroll
    for (int im = 0; im < 2; im++)
#pragma unroll
        for (int in = 0; in < 8; in++)
#pragma unroll
            for (int q = 0; q < 4; q++) c[im][in][q] = 0.0f;

    // prologue
    ldgA(0);
    issueB(0);
    issueB(1);
    stsA(0);
    ldgA(1);

    const int aRow = lane & 15;
    const int aKo  = ((lane >> 4) & 1) * 16;
    const int bRow = (lane & 7) + ((lane >> 4) << 3);
    const int bKo  = ((lane >> 3) & 1) * 16;

    for (int i = 0; i < nk; i++) {
        if (i + 1 < nk) { CP_WAIT1(); } else { CP_WAIT0(); }
        __syncthreads();                 // A(i) STS visible; all readers of A(i-1) done
        if (i + 1 < nk) stsA(i + 1);     // writes buf (i+1)&1, safe vs readers of A(i-1)
        if (i + 2 < nk) { ldgA(i + 2); issueB(i + 2); }

        const uint32_t aS = sA + (i & 1) * TBYTES;
        const uint32_t bS = sB + (i % 3) * TBYTES;
#pragma unroll
        for (int ks = 0; ks < 4; ks++) {
            uint32_t af[2][4];
#pragma unroll
            for (int im = 0; im < 2; im++)
                ldsm_x4(af[im], aS + SWZ128((wm + im * 16 + aRow) * 128 + ks * 32 + aKo));
#pragma unroll
            for (int nb = 0; nb < 4; nb++) {
                uint32_t bf[4];
                ldsm_x4(bf, bS + SWZ128((wn + nb * 16 + bRow) * 128 + ks * 32 + bKo));
#pragma unroll
                for (int im = 0; im < 2; im++) {
                    mma_f16(c[im][nb * 2 + 0], af[im], &bf[0]);
                    mma_f16(c[im][nb * 2 + 1], af[im], &bf[2]);
                }
            }
        }
    }

    // epilogue: gelu + store
    const int g  = lane >> 2;
    const int tg = lane & 3;
#pragma unroll
    for (int im = 0; im < 2; im++) {
#pragma unroll
        for (int in = 0; in < 8; in++) {
            const size_t r0 = bm + wm + im * 16 + g;
            const size_t r1 = r0 + 8;
            const size_t cc = bn + wn + in * 8 + tg * 2;
            float v0 = gelu_exact(c[im][in][0]);
            float v1 = gelu_exact(c[im][in][1]);
            float v2 = gelu_exact(c[im][in][2]);
            float v3 = gelu_exact(c[im][in][3]);
            *reinterpret_cast<float2*>(C + r0 * N + cc) = make_float2(v0, v1);
            *reinterpret_cast<float2*>(C + r1 * N + cc) = make_float2(v2, v3);
        }
    }
}

// --------------- fp32 -> fp16 conversion pass (fc2 only now) -----------------
__global__ __launch_bounds__(256) void cvt_half(const float4* __restrict__ in,
                                                __half2* __restrict__ out, int n4)
{
    int i = blockIdx.x * 256 + threadIdx.x;
    int stride = gridDim.x * 256;
    for (; i < n4; i += stride) {
        float4 v = in[i];
        out[i * 2 + 0] = __floats2half2_rn(v.x, v.y);
        out[i * 2 + 1] = __floats2half2_rn(v.z, v.w);
    }
}

// ------- fc1 transpose + cvt: [4096,1024] f32 -> [1024,4096] half ------------
__global__ void transpose_k(const float* __restrict__ in, __half* __restrict__ out,
                            int R, int Cc)
{
    __shared__ float t[32][33];
    int bx = blockIdx.x * 32;
    int by = blockIdx.y * 32;
    int x = threadIdx.x, y = threadIdx.y;
#pragma unroll
    for (int j = 0; j < 32; j += 8)
        t[y + j][x] = in[(size_t)(by + y + j) * Cc + bx + x];
    __syncthreads();
#pragma unroll
    for (int j = 0; j < 32; j += 8)
        out[(size_t)(bx + y + j) * R + by + x] = __float2half_rn(t[x][y + j]);
}

// fixup: attnT[t][s] = half( (sum_sk part[sk][s][t] + bias[t]) * mask[s][t] )
__global__ void fixup_k(const float* __restrict__ part, const float* __restrict__ bias,
                        const float* __restrict__ mask, __half* __restrict__ attnT)
{
    __shared__ float t[32][33];
    int bt = blockIdx.x * 32;
    int bs = blockIdx.y * 32;
    int x = threadIdx.x, y = threadIdx.y;
#pragma unroll
    for (int j = 0; j < 32; j += 8) {
        int s = bs + y + j, tc = bt + x;
        size_t idx = (size_t)s * 1024 + tc;
        float v = part[idx] + part[idx + 1048576] + part[idx + 2097152] + part[idx + 3145728];
        v = (v + bias[tc]) * mask[idx];
        t[y + j][x] = v;
    }
    __syncthreads();
#pragma unroll
    for (int j = 0; j < 32; j += 8)
        attnT[(size_t)(bt + y + j) * 1024 + bs + x] = __float2half_rn(t[x][y + j]);
}

// ---------------------------------------------------------------------------
extern "C" void kernel_launch(void* const* d_in, const int* in_sizes, int n_in,
                              void* d_out, int out_size)
{
    const float* x    = (const float*)d_in[0];
    const float* fc1  = (const float*)d_in[1];
    const float* fc2  = (const float*)d_in[2];
    const float* bias = (const float*)d_in[3];
    const float* mask = (const float*)d_in[4];
    float* out = (float*)d_out;

    __half *fc1T, *fc2h, *attnT;
    float* part;
    cudaGetSymbolAddress((void**)&fc1T, g_fc1T);
    cudaGetSymbolAddress((void**)&fc2h, g_fc2h);
    cudaGetSymbolAddress((void**)&part, g_part);
    cudaGetSymbolAddress((void**)&attnT, g_attnT);

    constexpr int SMEM1 = 6 * TBYTES;   // 98304 (GEMM1: 3-stage A + 3-stage B)
    constexpr int SMEM2 = 5 * TBYTES;   // 81920 (GEMM2: 2 A bufs + 3 B stages)
    cudaFuncSetAttribute(hgemm1, cudaFuncAttributeMaxDynamicSharedMemorySize, SMEM1);
    cudaFuncSetAttribute(hgemm2, cudaFuncAttributeMaxDynamicSharedMemorySize, SMEM2);

    // fc2 -> fp16
    cvt_half<<<1024, 256>>>((const float4*)fc2, (__half2*)fc2h, 1024 * 4096 / 4);

    // fc1T[s][d] = half(fc1[d][s])
    transpose_k<<<dim3(32, 128), dim3(32, 8)>>>(fc1, fc1T, 4096, 1024);

    // GEMM1 split-K=4: part[sk] = fc1T · fc2h^T over k slice
    hgemm1<<<dim3(8, 8, 4), 256, SMEM1>>>(fc1T, fc2h, part,
                                          1024, 1024, 4096, 4096, 1024);

    // reduce + bias + mask + transpose -> attnT [t][s] half
    fixup_k<<<dim3(32, 32), dim3(32, 8)>>>(part, bias, mask, attnT);

    // GEMM2 (inline x conversion): out = gelu(x · attnT^T)
    hgemm2<<<dim3(8, 384), 256, SMEM2>>>(x, attnT, out, 49152, 1024, 1024);
}

// round 12
// speedup vs baseline: 1.4179x; 1.4179x over previous
#include <cuda_runtime.h>
#include <cuda_fp16.h>
#include <cstdint>

// ============================================================================
// out = gelu( x @ ((fc1_w^T @ fc2_w^T + b) * mask) )   — fp32 in/out
// fp16 mma.sync.m16n8k16, f32 accumulate (R7 schedule = proven best).
// R12: cvt_x runs on a forked side stream, overlapping the weight chain
// (cvt_fc2 -> transpose -> GEMM1 -> fixup); join before GEMM2.
// ============================================================================

__device__ __half g_xh[49152 * 1024];
__device__ __half g_fc1T[1024 * 4096];
__device__ __half g_fc2h[1024 * 4096];
__device__ float  g_part[4 * 1024 * 1024];
__device__ __half g_attnT[1024 * 1024];

// ---------------- helpers ---------------------------------------------------
__device__ __forceinline__ uint32_t smem_u32(const void* p) {
    uint32_t a;
    asm("{ .reg .u64 t; cvta.to.shared.u64 t, %1; cvt.u32.u64 %0, t; }" : "=r"(a) : "l"(p));
    return a;
}
#define CP_ASYNC16(sdst, gsrc) \
    asm volatile("cp.async.cg.shared.global [%0], [%1], 16;" :: "r"(sdst), "l"(gsrc) : "memory")
#define CP_COMMIT() asm volatile("cp.async.commit_group;" ::: "memory")
#define CP_WAIT1()  asm volatile("cp.async.wait_group 1;" ::: "memory")
#define CP_WAIT0()  asm volatile("cp.async.wait_group 0;" ::: "memory")
#define SWZ128(off) ((off) ^ (((off) >> 3) & 0x70))

__device__ __forceinline__ void ldsm_x4(uint32_t* r, uint32_t addr) {
    asm volatile("ldmatrix.sync.aligned.m8n8.x4.shared.b16 {%0,%1,%2,%3}, [%4];"
                 : "=r"(r[0]), "=r"(r[1]), "=r"(r[2]), "=r"(r[3]) : "r"(addr));
}
// fp16 MMA, fp32 accumulate: C[16x8] += A[16x16] * B[16x8]
__device__ __forceinline__ void mma_f16(float c[4], const uint32_t a[4], const uint32_t* b) {
    asm volatile(
        "mma.sync.aligned.m16n8k16.row.col.f32.f16.f16.f32 "
        "{%0,%1,%2,%3}, {%4,%5,%6,%7}, {%8,%9}, {%0,%1,%2,%3};"
        : "+f"(c[0]), "+f"(c[1]), "+f"(c[2]), "+f"(c[3])
        : "r"(a[0]), "r"(a[1]), "r"(a[2]), "r"(a[3]), "r"(b[0]), "r"(b[1]));
}
__device__ __forceinline__ float gelu_exact(float u) {
    return 0.5f * u * (1.0f + erff(u * 0.7071067811865476f));
}

// ---------------------------------------------------------------------------
// fp16 GEMM (R7): CTA 128(m) x 128(n), 256 threads, warp tile 32x64.
// K chunks of 64 halfs (128B rows, SW128), 3-stage cp.async + wait_group(1),
// fragment double-buffering across the 4 k16 sub-steps.
// A [*,lda], B [*,ldb] k-major halfs, C = A·B^T fp32.
// EPI=1: gelu store; EPI=0: raw store. blockIdx.z = split-K slice.
// ---------------------------------------------------------------------------
constexpr int STAGES = 3;
constexpr int TBYTES = 128 * 128;   // 128 rows x 64 halfs

template <int EPI>
__global__ __launch_bounds__(256, 2) void hgemm(
    const __half* __restrict__ A, const __half* __restrict__ B, float* __restrict__ C,
    int M, int N, int lda, int ldb, int kSplit)
{
    extern __shared__ __align__(1024) char smem[];
    const uint32_t sb = smem_u32(smem);
    const int tid  = threadIdx.x;
    const int lane = tid & 31;
    const int wid  = tid >> 5;
    const int wm   = (wid & 3) * 32;
    const int wn   = (wid >> 2) * 64;
    const size_t bm = (size_t)blockIdx.y * 128;
    const size_t bn = (size_t)blockIdx.x * 128;

    const __half* Ab = A + (size_t)blockIdx.z * kSplit;
    const __half* Bb = B + (size_t)blockIdx.z * kSplit;

    const int nk = kSplit / 64;

    const int lr = tid >> 3;        // 0..31
    const int lc = tid & 7;         // 16B (8-half) column
    auto issue = [&](int chunk) {
        const int buf = chunk % STAGES;
        const uint32_t aBase = sb + buf * TBYTES;
        const uint32_t bBase = sb + STAGES * TBYTES + buf * TBYTES;
        const __half* ga = Ab + (bm + lr) * (size_t)lda + chunk * 64 + lc * 8;
        const __half* gb = Bb + (bn + lr) * (size_t)ldb + chunk * 64 + lc * 8;
#pragma unroll
        for (int j = 0; j < 4; j++) {
            CP_ASYNC16(aBase + SWZ128((lr + j * 32) * 128 + lc * 16), ga + (size_t)(j * 32) * lda);
            CP_ASYNC16(bBase + SWZ128((lr + j * 32) * 128 + lc * 16), gb + (size_t)(j * 32) * ldb);
        }
        CP_COMMIT();
    };

    float c[2][8][4];
#pragma unroll
    for (int im = 0; im < 2; im++)
#pragma unroll
        for (int in = 0; in < 8; in++)
#pragma unroll
            for (int q = 0; q < 4; q++) c[im][in][q] = 0.0f;

    issue(0);
    issue(1);

    // ldmatrix addressing (see R6): A x4 = 16m x 16k frag in mma reg order;
    // B x4 = 16n x 16k -> {b0(n0-7), b1(n0-7), b0(n8-15), b1(n8-15)}.
    const int aRow = lane & 15;
    const int aKo  = ((lane >> 4) & 1) * 16;
    const int bRow = (lane & 7) + ((lane >> 4) << 3);
    const int bKo  = ((lane >> 3) & 1) * 16;

    auto loadA = [&](uint32_t (*f)[4], uint32_t aS, int ks) {
#pragma unroll
        for (int im = 0; im < 2; im++)
            ldsm_x4(f[im], aS + SWZ128((wm + im * 16 + aRow) * 128 + ks * 32 + aKo));
    };
    auto loadB = [&](uint32_t (*f)[4], uint32_t bS, int ks) {
#pragma unroll
        for (int nb = 0; nb < 4; nb++)
            ldsm_x4(f[nb], bS + SWZ128((wn + nb * 16 + bRow) * 128 + ks * 32 + bKo));
    };

    for (int i = 0; i < nk; i++) {
        if (i + 1 < nk) { CP_WAIT1(); } else { CP_WAIT0(); }
        __syncthreads();
        if (i + 2 < nk) issue(i + 2);

        const int buf = i % STAGES;
        const uint32_t aS = sb + buf * TBYTES;
        const uint32_t bS = sb + STAGES * TBYTES + buf * TBYTES;

        uint32_t af[2][2][4];   // [pingpong][im][4]
        uint32_t bf[2][4][4];   // [pingpong][nb][4]
        loadA(af[0], aS, 0);
        loadB(bf[0], bS, 0);
#pragma unroll
        for (int ks = 0; ks < 4; ks++) {   // 4 x k16 (32B each) per 128B chunk
            const int cur = ks & 1, nxt = cur ^ 1;
            if (ks < 3) {                  // prefetch ks+1 while MMAing ks
                loadA(af[nxt], aS, ks + 1);
                loadB(bf[nxt], bS, ks + 1);
            }
#pragma unroll
            for (int im = 0; im < 2; im++)
#pragma unroll
                for (int nb = 0; nb < 4; nb++) {
                    mma_f16(c[im][nb * 2 + 0], af[cur][im], &bf[cur][nb][0]);
                    mma_f16(c[im][nb * 2 + 1], af[cur][im], &bf[cur][nb][2]);
                }
        }
    }

    // ---------------- epilogue ----------------
    float* Cb = C + (size_t)blockIdx.z * ((size_t)M * N);
    const int g  = lane >> 2;
    const int tg = lane & 3;
#pragma unroll
    for (int im = 0; im < 2; im++) {
#pragma unroll
        for (int in = 0; in < 8; in++) {
            const size_t r0 = bm + wm + im * 16 + g;
            const size_t r1 = r0 + 8;
            const size_t cc = bn + wn + in * 8 + tg * 2;
            float v0 = c[im][in][0], v1 = c[im][in][1];
            float v2 = c[im][in][2], v3 = c[im][in][3];
            if (EPI == 1) {
                v0 = gelu_exact(v0); v1 = gelu_exact(v1);
                v2 = gelu_exact(v2); v3 = gelu_exact(v3);
            }
            *reinterpret_cast<float2*>(Cb + r0 * N + cc) = make_float2(v0, v1);
            *reinterpret_cast<float2*>(Cb + r1 * N + cc) = make_float2(v2, v3);
        }
    }
}

// --------------- fp32 -> fp16 conversion pass --------------------------------
__global__ __launch_bounds__(256) void cvt_half(const float4* __restrict__ in,
                                                __half2* __restrict__ out, int n4)
{
    int i = blockIdx.x * 256 + threadIdx.x;
    int stride = gridDim.x * 256;
    for (; i < n4; i += stride) {
        float4 v = in[i];
        out[i * 2 + 0] = __floats2half2_rn(v.x, v.y);
        out[i * 2 + 1] = __floats2half2_rn(v.z, v.w);
    }
}

// ------- fc1 transpose + cvt: [4096,1024] f32 -> [1024,4096] half ------------
__global__ void transpose_k(const float* __restrict__ in, __half* __restrict__ out,
                            int R, int Cc)
{
    __shared__ float t[32][33];
    int bx = blockIdx.x * 32;
    int by = blockIdx.y * 32;
    int x = threadIdx.x, y = threadIdx.y;
#pragma unroll
    for (int j = 0; j < 32; j += 8)
        t[y + j][x] = in[(size_t)(by + y + j) * Cc + bx + x];
    __syncthreads();
#pragma unroll
    for (int j = 0; j < 32; j += 8)
        out[(size_t)(bx + y + j) * R + by + x] = __float2half_rn(t[x][y + j]);
}

// fixup: attnT[t][s] = half( (sum_sk part[sk][s][t] + bias[t]) * mask[s][t] )
__global__ void fixup_k(const float* __restrict__ part, const float* __restrict__ bias,
                        const float* __restrict__ mask, __half* __restrict__ attnT)
{
    __shared__ float t[32][33];
    int bt = blockIdx.x * 32;
    int bs = blockIdx.y * 32;
    int x = threadIdx.x, y = threadIdx.y;
#pragma unroll
    for (int j = 0; j < 32; j += 8) {
        int s = bs + y + j, tc = bt + x;
        size_t idx = (size_t)s * 1024 + tc;
        float v = part[idx] + part[idx + 1048576] + part[idx + 2097152] + part[idx + 3145728];
        v = (v + bias[tc]) * mask[idx];
        t[y + j][x] = v;
    }
    __syncthreads();
#pragma unroll
    for (int j = 0; j < 32; j += 8)
        attnT[(size_t)(bt + y + j) * 1024 + bs + x] = __float2half_rn(t[x][y + j]);
}

// ---------------------------------------------------------------------------
extern "C" void kernel_launch(void* const* d_in, const int* in_sizes, int n_in,
                              void* d_out, int out_size)
{
    const float* x    = (const float*)d_in[0];
    const float* fc1  = (const float*)d_in[1];
    const float* fc2  = (const float*)d_in[2];
    const float* bias = (const float*)d_in[3];
    const float* mask = (const float*)d_in[4];
    float* out = (float*)d_out;

    __half *xh, *fc1T, *fc2h, *attnT;
    float* part;
    cudaGetSymbolAddress((void**)&xh, g_xh);
    cudaGetSymbolAddress((void**)&fc1T, g_fc1T);
    cudaGetSymbolAddress((void**)&fc2h, g_fc2h);
    cudaGetSymbolAddress((void**)&part, g_part);
    cudaGetSymbolAddress((void**)&attnT, g_attnT);

    constexpr int SMEM = 2 * STAGES * TBYTES;   // 98304
    cudaFuncSetAttribute(hgemm<0>, cudaFuncAttributeMaxDynamicSharedMemorySize, SMEM);
    cudaFuncSetAttribute(hgemm<1>, cudaFuncAttributeMaxDynamicSharedMemorySize, SMEM);

    // ---- fork: cvt_x on a side stream, weight chain on the main stream ----
    cudaStream_t side;
    cudaEvent_t evFork, evJoin;
    cudaStreamCreateWithFlags(&side, cudaStreamNonBlocking);
    cudaEventCreateWithFlags(&evFork, cudaEventDisableTiming);
    cudaEventCreateWithFlags(&evJoin, cudaEventDisableTiming);

    cudaEventRecord(evFork, 0);
    cudaStreamWaitEvent(side, evFork, 0);

    // side branch: x -> fp16 (DRAM-bound, ~45-50us)
    cvt_half<<<4736, 256, 0, side>>>((const float4*)x, (__half2*)xh, 49152 * 1024 / 4);
    cudaEventRecord(evJoin, side);

    // main branch: weight chain (tensor-bound, ~48us)
    cvt_half<<<1024, 256>>>((const float4*)fc2, (__half2*)fc2h, 1024 * 4096 / 4);
    transpose_k<<<dim3(32, 128), dim3(32, 8)>>>(fc1, fc1T, 4096, 1024);
    hgemm<0><<<dim3(8, 8, 4), 256, SMEM>>>(fc1T, fc2h, part,
                                           1024, 1024, 4096, 4096, 1024);
    fixup_k<<<dim3(32, 32), dim3(32, 8)>>>(part, bias, mask, attnT);

    // join, then GEMM2 consumes both branches
    cudaStreamWaitEvent(0, evJoin, 0);
    hgemm<1><<<dim3(8, 384, 1), 256, SMEM>>>(xh, attnT, out,
                                             49152, 1024, 1024, 1024, 1024);
    // NOTE: side/evFork/evJoin intentionally not destroyed here — destroying
    // capture-referenced handles mid-capture is illegal; the handful of calls
    // the harness makes leaks a few KB of host-side handles, which is safe.
}